// round 11
// baseline (speedup 1.0000x reference)
#include <cuda_runtime.h>
#include <math.h>
#include <stdint.h>

#define Bn   512
#define Nn   199
#define Hn   4
#define Fn   64
#define Un   64
#define OUTC 455           // H*U + N
#define MT   13            // m16 tiles covering 200 rows (208)
#define KT   25            // k/j tiles of 8 covering 200
#define FT   8             // f/u tiles of 8 (64)
#define THREADS 512
#define XST  200           // XsT row stride (== 8 mod 32: conflict-free float2)

// Preprocessed operand banks (global, L2-resident)
__device__ float g_Ga[Hn * MT * KT * 32 * 4];  // feat A-frags: G[m][n] tf32
__device__ float g_Kb[Hn * KT * FT * 32 * 2];  // dense B-frags: K[f][j] tf32
__device__ float g_Fb[Hn * FT * FT * 32 * 2];  // fc B-frags: fc[f][u] tf32
__device__ float g_Ac[MT * KT * 32 * 4];       // adjacency in C-frag layout

#define GA_N (Hn * MT * KT * 128)
#define KB_N (Hn * KT * FT * 64)
#define FB_N (Hn * FT * FT * 64)
#define AC_N (MT * KT * 128)

__device__ __forceinline__ float tf32r(float x) {
    asm("cvt.rna.tf32.f32 %0, %0;" : "+f"(x)); return x;
}
__device__ __forceinline__ void mma_tf32(float c[4], const uint32_t a[4],
                                         uint32_t b0, uint32_t b1) {
    asm volatile(
        "mma.sync.aligned.m16n8k8.row.col.f32.tf32.tf32.f32 "
        "{%0,%1,%2,%3}, {%4,%5,%6,%7}, {%8,%9}, {%0,%1,%2,%3};"
        : "+f"(c[0]), "+f"(c[1]), "+f"(c[2]), "+f"(c[3])
        : "r"(a[0]), "r"(a[1]), "r"(a[2]), "r"(a[3]), "r"(b0), "r"(b1));
}
// C-fragment (r,2c even/odd pairs) -> A-fragment (r,k) of the same 8-wide tile
__device__ __forceinline__ void c2a(const float c[4], float a[4], int lane) {
    int s0 = (lane & ~3) | ((lane & 3) >> 1);
    int s1 = s0 + 2;
    float v0 = __shfl_sync(~0u, c[0], s0), v1 = __shfl_sync(~0u, c[1], s0);
    float v2 = __shfl_sync(~0u, c[2], s0), v3 = __shfl_sync(~0u, c[3], s0);
    float w0 = __shfl_sync(~0u, c[0], s1), w1 = __shfl_sync(~0u, c[1], s1);
    float w2 = __shfl_sync(~0u, c[2], s1), w3 = __shfl_sync(~0u, c[3], s1);
    bool odd = lane & 1;
    a[0] = odd ? v1 : v0;  a[1] = odd ? v3 : v2;
    a[2] = odd ? w1 : w0;  a[3] = odd ? w3 : w2;
}

// ---------------- fused operand prep (single launch) ----------------
__global__ void prep_all(const float* __restrict__ A, const float* __restrict__ P,
                         const float* __restrict__ KER, const float* __restrict__ FC) {
    int t = blockIdx.x * blockDim.x + threadIdx.x;
    if (t < GA_N) {
        int i = t & 3, lane = (t >> 2) & 31, rest = t >> 7;
        int kt = rest % KT; rest /= KT;
        int mt = rest % MT; int h = rest / MT;
        int row = (lane >> 2) + (i & 1) * 8;
        int kc  = (lane & 3) + ((i >> 1) << 2);
        int m = 16 * mt + row, n = 8 * kt + kc;
        float v = 0.f;
        if (m < Nn && n < Nn) v = tf32r(A[n * Nn + m] * P[(h * Nn + n) * Nn + m]);
        g_Ga[t] = v;
        return;
    }
    t -= GA_N;
    if (t < KB_N) {
        int i = t & 1, lane = (t >> 1) & 31, rest = t >> 6;
        int kt = rest & 7; rest >>= 3;
        int jt = rest % KT; int h = rest / KT;
        int f = 8 * kt + (lane & 3) + 4 * i;
        int j = 8 * jt + (lane >> 2);
        g_Kb[t] = (j < Nn) ? tf32r(KER[(h * Fn + f) * Nn + j]) : 0.f;
        return;
    }
    t -= KB_N;
    if (t < FB_N) {
        int i = t & 1, lane = (t >> 1) & 31, rest = t >> 6;
        int kt = rest & 7; rest >>= 3;
        int ut = rest & 7; int h = rest >> 3;
        int f = 8 * kt + (lane & 3) + 4 * i;
        int u = 8 * ut + (lane >> 2);
        g_Fb[t] = tf32r(FC[(h * Fn + f) * Un + u]);
        return;
    }
    t -= FB_N;
    if (t < AC_N) {
        int i = t & 3, lane = (t >> 2) & 31, rest = t >> 7;
        int jt = rest % KT; int mt = rest / KT;
        int r = (lane >> 2) + (i >> 1) * 8;
        int j = 8 * jt + 2 * (lane & 3) + (i & 1);
        int m = 16 * mt + r;
        g_Ac[t] = (m < Nn && j < Nn) ? A[m * Nn + j] : 0.f;
    }
}

// ---------------- main fused kernel ----------------
__global__ __launch_bounds__(THREADS, 1)
void gc_kernel(const float* __restrict__ X, const float* __restrict__ B1,
               const float* __restrict__ B2, float* __restrict__ out)
{
    extern __shared__ float smem[];
    float* XsT = smem;                 // [64][XST] tf32 X^T, pair-permuted cols
    float* b1s = XsT + Fn * XST;       // [200]
    float* b2s = b1s + 200;            // [64]

    const int b = blockIdx.x / Hn;
    const int h = blockIdx.x - b * Hn;
    const int tid = threadIdx.x;
    const int w = tid >> 5;
    const int lane = tid & 31;
    const bool last_h = (h == Hn - 1);

    for (int i = tid; i < 200 * Fn; i += THREADS) {
        int n = i >> 6, f = i & 63;
        float v = (n < Nn) ? X[((size_t)b * Nn + n) * Fn + f] : 0.f;
        // pair permutation: slot pair 2c holds (n=c, n=c+4) of each 8-tile
        int col = (n & ~7) | ((n & 3) << 1) | ((n >> 2) & 1);
        XsT[f * XST + col] = tf32r(v);
    }
    for (int i = tid; i < 200; i += THREADS) b1s[i] = (i < Nn) ? B1[h * Nn + i] : 0.f;
    if (tid < Un) b2s[tid] = B2[h * Un + tid];
    __syncthreads();

    if (w >= MT) return;
    const int m0 = 16 * w;
    const int mA = m0 + (lane >> 2);        // row for c0/c1
    const int mB = mA + 8;                  // row for c2/c3
    const int pairOff = 2 * (lane & 3);     // pair slot within tile
    const int bRow = (lane >> 2);           // n-dim row within B tile

    // ======== FEAT: fC[ft] = G(m-tile) @ X  (k = 200 nodes) ========
    float fC[FT][4];
    #pragma unroll
    for (int t = 0; t < FT; t++) { fC[t][0]=fC[t][1]=fC[t][2]=fC[t][3]=0.f; }
    {
        const float4* gaP = ((const float4*)g_Ga) + ((size_t)(h * MT + w) * KT) * 32 + lane;
        float4 ga = __ldg(gaP);
        #pragma unroll 1
        for (int kt = 0; kt < KT; kt++) {
            float4 gan = (kt + 1 < KT) ? __ldg(gaP + (kt + 1) * 32) : ga;
            uint32_t a[4] = { __float_as_uint(ga.x), __float_as_uint(ga.y),
                              __float_as_uint(ga.z), __float_as_uint(ga.w) };
            #pragma unroll
            for (int ft = 0; ft < FT; ft++) {
                float2 xv = *(const float2*)&XsT[(8 * ft + bRow) * XST + 8 * kt + pairOff];
                mma_tf32(fC[ft], a, __float_as_uint(xv.x), __float_as_uint(xv.y));
            }
            ga = gan;
        }
    }
    // permute feat C -> A fragments (k = f)
    uint32_t fA[FT][4];
    #pragma unroll
    for (int t = 0; t < FT; t++) {
        float a4[4]; c2a(fC[t], a4, lane);
        #pragma unroll
        for (int q = 0; q < 4; q++) fA[t][q] = __float_as_uint(tf32r(a4[q]));
    }

    // ======== DENSE + masked exp + NODE: two independent j-streams ========
    float nC[FT][4];
    #pragma unroll
    for (int t = 0; t < FT; t++) { nC[t][0]=nC[t][1]=nC[t][2]=nC[t][3]=0.f; }
    float sA0 = 0.f, sA1 = 0.f, sB0 = 0.f, sB1 = 0.f;

    const float2* kbP = ((const float2*)g_Kb) + ((size_t)h * KT * FT) * 32 + lane;
    const float4* acP = ((const float4*)g_Ac) + ((size_t)w * KT) * 32 + lane;

    #pragma unroll 1
    for (int it = 0; it < 13; it++) {
        const int jtA = 2 * it;
        const bool hasB = (it < 12);
        const int jtB = hasB ? (2 * it + 1) : 23;   // clamp; contributions zeroed

        float2 kbA[FT], kbB[FT];
        #pragma unroll
        for (int kt = 0; kt < FT; kt++) {
            kbA[kt] = __ldg(kbP + (jtA * FT + kt) * 32);
            kbB[kt] = __ldg(kbP + (jtB * FT + kt) * 32);
        }
        float4 acA = __ldg(acP + jtA * 32);
        float4 acB = hasB ? __ldg(acP + jtB * 32) : make_float4(0.f, 0.f, 0.f, 0.f);

        // two independent dual-accumulator dense chains
        float dA0[4] = {0,0,0,0}, dA1[4] = {0,0,0,0};
        float dB0[4] = {0,0,0,0}, dB1[4] = {0,0,0,0};
        #pragma unroll
        for (int kt = 0; kt < FT; kt += 2) {
            mma_tf32(dA0, fA[kt],     __float_as_uint(kbA[kt].x),     __float_as_uint(kbA[kt].y));
            mma_tf32(dB0, fA[kt],     __float_as_uint(kbB[kt].x),     __float_as_uint(kbB[kt].y));
            mma_tf32(dA1, fA[kt + 1], __float_as_uint(kbA[kt + 1].x), __float_as_uint(kbA[kt + 1].y));
            mma_tf32(dB1, fA[kt + 1], __float_as_uint(kbB[kt + 1].x), __float_as_uint(kbB[kt + 1].y));
        }

        const int jA = 8 * jtA + pairOff;
        const int jB = 8 * jtB + pairOff;
        float2 b1A = *(const float2*)&b1s[jA];
        float2 b1B = *(const float2*)&b1s[jB];
        float eA0 = acA.x * __expf(dA0[0] + dA1[0] + b1A.x);
        float eA1 = acA.y * __expf(dA0[1] + dA1[1] + b1A.y);
        float eA2 = acA.z * __expf(dA0[2] + dA1[2] + b1A.x);
        float eA3 = acA.w * __expf(dA0[3] + dA1[3] + b1A.y);
        float eB0 = acB.x * __expf(dB0[0] + dB1[0] + b1B.x);
        float eB1 = acB.y * __expf(dB0[1] + dB1[1] + b1B.y);
        float eB2 = acB.z * __expf(dB0[2] + dB1[2] + b1B.x);
        float eB3 = acB.w * __expf(dB0[3] + dB1[3] + b1B.y);
        sA0 += eA0 + eA1; sA1 += eA2 + eA3;
        sB0 += eB0 + eB1; sB1 += eB2 + eB3;

        if (last_h) {   // raw (unnormalized) mask; rescaled by same thread later
            if (mA < Nn) {
                float* o = out + ((size_t)b * Nn + mA) * OUTC + Hn * Un;
                o[jA] = eA0; if (jA < 198) o[jA + 1] = eA1;
                if (hasB) { o[jB] = eB0; if (jB < 198) o[jB + 1] = eB1; }
            }
            if (mB < Nn) {
                float* o = out + ((size_t)b * Nn + mB) * OUTC + Hn * Un;
                o[jA] = eA2; if (jA < 198) o[jA + 1] = eA3;
                if (hasB) { o[jB] = eB2; if (jB < 198) o[jB + 1] = eB3; }
            }
        }
        // node += e-tiles @ X (two independent c2a chains)
        float ecA[4] = {eA0, eA1, eA2, eA3}, eaA[4];
        float ecB[4] = {eB0, eB1, eB2, eB3}, eaB[4];
        c2a(ecA, eaA, lane);
        c2a(ecB, eaB, lane);
        uint32_t uA[4], uB[4];
        #pragma unroll
        for (int q = 0; q < 4; q++) {
            uA[q] = __float_as_uint(tf32r(eaA[q]));
            uB[q] = __float_as_uint(tf32r(eaB[q]));
        }
        #pragma unroll
        for (int ft = 0; ft < FT; ft++) {
            float2 xvA = *(const float2*)&XsT[(8 * ft + bRow) * XST + 8 * jtA + pairOff];
            float2 xvB = *(const float2*)&XsT[(8 * ft + bRow) * XST + 8 * jtB + pairOff];
            mma_tf32(nC[ft], uA, __float_as_uint(xvA.x), __float_as_uint(xvA.y));
            mma_tf32(nC[ft], uB, __float_as_uint(xvB.x), __float_as_uint(xvB.y));
        }
    }
    float s0 = sA0 + sB0, s1 = sA1 + sB1;
    // row sums across the 4 lanes of each row group
    s0 += __shfl_xor_sync(~0u, s0, 1); s0 += __shfl_xor_sync(~0u, s0, 2);
    s1 += __shfl_xor_sync(~0u, s1, 1); s1 += __shfl_xor_sync(~0u, s1, 2);
    float inv0 = 1.f / s0, inv1 = 1.f / s1;

    if (last_h) {   // normalize mask in-place (same thread wrote these)
        #pragma unroll 1
        for (int jt = 0; jt < KT; jt++) {
            int j = 8 * jt + pairOff;
            if (mA < Nn) {
                float* o = out + ((size_t)b * Nn + mA) * OUTC + Hn * Un + j;
                o[0] *= inv0; if (j < 198) o[1] *= inv0;
            }
            if (mB < Nn) {
                float* o = out + ((size_t)b * Nn + mB) * OUTC + Hn * Un + j;
                o[0] *= inv1; if (j < 198) o[1] *= inv1;
            }
        }
    }
    // normalize node accumulators
    #pragma unroll
    for (int t = 0; t < FT; t++) {
        nC[t][0] *= inv0; nC[t][1] *= inv0;
        nC[t][2] *= inv1; nC[t][3] *= inv1;
    }
    // permute node C -> A fragments (k = f)
    uint32_t nA[FT][4];
    #pragma unroll
    for (int t = 0; t < FT; t++) {
        float a4[4]; c2a(nC[t], a4, lane);
        #pragma unroll
        for (int q = 0; q < 4; q++) nA[t][q] = __float_as_uint(tf32r(a4[q]));
    }

    // ======== FC: out = node @ fc + b2 ========
    const float2* fbP = ((const float2*)g_Fb) + ((size_t)h * FT * FT) * 32 + lane;
    #pragma unroll 1
    for (int ut = 0; ut < FT; ut++) {
        float oC[4] = {0.f, 0.f, 0.f, 0.f};
        #pragma unroll
        for (int kt = 0; kt < FT; kt++) {
            float2 fb = __ldg(fbP + (ut * FT + kt) * 32);
            mma_tf32(oC, nA[kt], __float_as_uint(fb.x), __float_as_uint(fb.y));
        }
        int u = 8 * ut + pairOff;
        float2 b2v = *(const float2*)&b2s[u];
        if (mA < Nn) {
            float* o = out + ((size_t)b * Nn + mA) * OUTC + h * Un + u;
            o[0] = oC[0] + b2v.x; o[1] = oC[1] + b2v.y;
        }
        if (mB < Nn) {
            float* o = out + ((size_t)b * Nn + mB) * OUTC + h * Un + u;
            o[0] = oC[2] + b2v.x; o[1] = oC[3] + b2v.y;
        }
    }
}

static const size_t SMEM_BYTES = (size_t)(Fn * XST + 200 + Un) * 4;

extern "C" void kernel_launch(void* const* d_in, const int* in_sizes, int n_in,
                              void* d_out, int out_size) {
    const float* X   = (const float*)d_in[0];
    const float* A   = (const float*)d_in[1];
    const float* KER = (const float*)d_in[2];
    const float* P   = (const float*)d_in[3];
    const float* FC  = (const float*)d_in[4];
    const float* B1  = (const float*)d_in[5];
    const float* B2  = (const float*)d_in[6];
    float* out = (float*)d_out;

    const int PREP_TOTAL = GA_N + KB_N + FB_N + AC_N;
    prep_all<<<(PREP_TOTAL + 255) / 256, 256>>>(A, P, KER, FC);

    cudaFuncSetAttribute(gc_kernel, cudaFuncAttributeMaxDynamicSharedMemorySize,
                         (int)SMEM_BYTES);
    gc_kernel<<<Bn * Hn, THREADS, SMEM_BYTES>>>(X, B1, B2, out);
}

// round 13
// speedup vs baseline: 1.8026x; 1.8026x over previous
#include <cuda_runtime.h>
#include <math.h>
#include <stdint.h>

#define Bn   512
#define Nn   199
#define Hn   4
#define Fn   64
#define Un   64
#define OUTC 455           // H*U + N
#define MT   13            // m16 tiles covering 200 rows (208)
#define KT   25            // k/j tiles of 8 covering 200
#define FT   8             // f/u tiles of 8 (64)
#define THREADS 512
#define XST  200           // XsT row stride (== 8 mod 32: conflict-free float2)
#define EBW  (16 * 200)    // e-buffer floats per warp

// Preprocessed operand banks (global, L2-resident)
__device__ float g_Ga[Hn * MT * KT * 32 * 4];  // feat A-frags: G[m][n] tf32
__device__ float g_Kb[Hn * KT * FT * 32 * 2];  // dense B-frags: K[f][j] tf32
__device__ float g_Fb[Hn * FT * FT * 32 * 2];  // fc B-frags: fc[f][u] tf32
__device__ float g_Ac[MT * KT * 32 * 4];       // adjacency in C-frag layout

#define GA_N (Hn * MT * KT * 128)
#define KB_N (Hn * KT * FT * 64)
#define FB_N (Hn * FT * FT * 64)
#define AC_N (MT * KT * 128)

__device__ __forceinline__ float tf32r(float x) {
    asm("cvt.rna.tf32.f32 %0, %0;" : "+f"(x)); return x;
}
__device__ __forceinline__ void mma_tf32(float c[4], const uint32_t a[4],
                                         uint32_t b0, uint32_t b1) {
    asm volatile(
        "mma.sync.aligned.m16n8k8.row.col.f32.tf32.tf32.f32 "
        "{%0,%1,%2,%3}, {%4,%5,%6,%7}, {%8,%9}, {%0,%1,%2,%3};"
        : "+f"(c[0]), "+f"(c[1]), "+f"(c[2]), "+f"(c[3])
        : "r"(a[0]), "r"(a[1]), "r"(a[2]), "r"(a[3]), "r"(b0), "r"(b1));
}
// C-fragment (r,2c even/odd pairs) -> A-fragment (r,k) of the same 8-wide tile
// Output order matches PTX m16n8k8.tf32 A layout:
//   a0=(g, t), a1=(g+8, t), a2=(g, t+4), a3=(g+8, t+4)
__device__ __forceinline__ void c2a(const float c[4], float a[4], int lane) {
    int s0 = (lane & ~3) | ((lane & 3) >> 1);
    int s1 = s0 + 2;
    float v0 = __shfl_sync(~0u, c[0], s0), v1 = __shfl_sync(~0u, c[1], s0);
    float v2 = __shfl_sync(~0u, c[2], s0), v3 = __shfl_sync(~0u, c[3], s0);
    float w0 = __shfl_sync(~0u, c[0], s1), w1 = __shfl_sync(~0u, c[1], s1);
    float w2 = __shfl_sync(~0u, c[2], s1), w3 = __shfl_sync(~0u, c[3], s1);
    bool odd = lane & 1;
    a[0] = odd ? v1 : v0;  a[1] = odd ? v3 : v2;
    a[2] = odd ? w1 : w0;  a[3] = odd ? w3 : w2;
}

// ---------------- fused operand prep (single launch) ----------------
__global__ void prep_all(const float* __restrict__ A, const float* __restrict__ P,
                         const float* __restrict__ KER, const float* __restrict__ FC) {
    int t = blockIdx.x * blockDim.x + threadIdx.x;
    if (t < GA_N) {
        int i = t & 3, lane = (t >> 2) & 31, rest = t >> 7;
        int kt = rest % KT; rest /= KT;
        int mt = rest % MT; int h = rest / MT;
        int row = (lane >> 2) + (i & 1) * 8;
        int kc  = (lane & 3) + ((i >> 1) << 2);
        int m = 16 * mt + row, n = 8 * kt + kc;
        float v = 0.f;
        if (m < Nn && n < Nn) v = tf32r(A[n * Nn + m] * P[(h * Nn + n) * Nn + m]);
        g_Ga[t] = v;
        return;
    }
    t -= GA_N;
    if (t < KB_N) {
        int i = t & 1, lane = (t >> 1) & 31, rest = t >> 6;
        int kt = rest & 7; rest >>= 3;
        int jt = rest % KT; int h = rest / KT;
        int f = 8 * kt + (lane & 3) + 4 * i;
        int j = 8 * jt + (lane >> 2);
        g_Kb[t] = (j < Nn) ? tf32r(KER[(h * Fn + f) * Nn + j]) : 0.f;
        return;
    }
    t -= KB_N;
    if (t < FB_N) {
        int i = t & 1, lane = (t >> 1) & 31, rest = t >> 6;
        int kt = rest & 7; rest >>= 3;
        int ut = rest & 7; int h = rest >> 3;
        int f = 8 * kt + (lane & 3) + 4 * i;
        int u = 8 * ut + (lane >> 2);
        g_Fb[t] = tf32r(FC[(h * Fn + f) * Un + u]);
        return;
    }
    t -= FB_N;
    if (t < AC_N) {
        int i = t & 3, lane = (t >> 2) & 31, rest = t >> 7;
        int jt = rest % KT; int mt = rest / KT;
        int r = (lane >> 2) + (i >> 1) * 8;
        int j = 8 * jt + 2 * (lane & 3) + (i & 1);
        int m = 16 * mt + r;
        g_Ac[t] = (m < Nn && j < Nn) ? A[m * Nn + j] : 0.f;
    }
}

// ---------------- main fused kernel ----------------
__global__ __launch_bounds__(THREADS, 1)
void gc_kernel(const float* __restrict__ X, const float* __restrict__ B1,
               const float* __restrict__ B2, float* __restrict__ out)
{
    extern __shared__ float smem[];
    float* XsT  = smem;                 // [64][XST] tf32 X^T, pair-permuted cols
    float* b1s  = XsT + Fn * XST;       // [200]
    float* b2s  = b1s + 200;            // [64]
    float* ebuf = b2s + 64;             // [MT][16][200] per-warp e staging

    const int b = blockIdx.x / Hn;
    const int h = blockIdx.x - b * Hn;
    const int tid = threadIdx.x;
    const int w = tid >> 5;
    const int lane = tid & 31;
    const bool last_h = (h == Hn - 1);

    for (int i = tid; i < 200 * Fn; i += THREADS) {
        int n = i >> 6, f = i & 63;
        float v = (n < Nn) ? X[((size_t)b * Nn + n) * Fn + f] : 0.f;
        // pair permutation: slot pair 2c holds (n=c, n=c+4) of each 8-tile
        int col = (n & ~7) | ((n & 3) << 1) | ((n >> 2) & 1);
        XsT[f * XST + col] = tf32r(v);
    }
    for (int i = tid; i < 200; i += THREADS) b1s[i] = (i < Nn) ? B1[h * Nn + i] : 0.f;
    if (tid < Un) b2s[tid] = B2[h * Un + tid];
    __syncthreads();

    if (w >= MT) return;
    const int m0 = 16 * w;
    const int rl = lane >> 2;               // local row within m16 tile
    const int mA = m0 + rl;                 // row for c0/c1
    const int mB = mA + 8;                  // row for c2/c3
    const int pairOff = 2 * (lane & 3);     // pair slot within tile
    const int bRow = rl;                    // n-dim row within B tile
    float* eb = ebuf + w * EBW;             // [16][200]

    // ======== FEAT: fC[ft] = G(m-tile) @ X  (k = 200 nodes) ========
    float fC[FT][4];
    #pragma unroll
    for (int t = 0; t < FT; t++) { fC[t][0]=fC[t][1]=fC[t][2]=fC[t][3]=0.f; }
    {
        const float4* gaP = ((const float4*)g_Ga) + ((size_t)(h * MT + w) * KT) * 32 + lane;
        float4 ga = __ldg(gaP);
        #pragma unroll 1
        for (int kt = 0; kt < KT; kt++) {
            float4 gan = (kt + 1 < KT) ? __ldg(gaP + (kt + 1) * 32) : ga;
            uint32_t a[4] = { __float_as_uint(ga.x), __float_as_uint(ga.y),
                              __float_as_uint(ga.z), __float_as_uint(ga.w) };
            #pragma unroll
            for (int ft = 0; ft < FT; ft++) {
                float2 xv = *(const float2*)&XsT[(8 * ft + bRow) * XST + 8 * kt + pairOff];
                mma_tf32(fC[ft], a, __float_as_uint(xv.x), __float_as_uint(xv.y));
            }
            ga = gan;
        }
    }
    // permute feat C -> A fragments (k = f)
    uint32_t fA[FT][4];
    #pragma unroll
    for (int t = 0; t < FT; t++) {
        float a4[4]; c2a(fC[t], a4, lane);
        #pragma unroll
        for (int q = 0; q < 4; q++) fA[t][q] = __float_as_uint(tf32r(a4[q]));
    }

    // ======== PASS A: DENSE + masked exp -> smem e-buffer ========
    float s0 = 0.f, s1 = 0.f;
    {
        const float2* kbP = ((const float2*)g_Kb) + ((size_t)h * KT * FT) * 32 + lane;
        const float4* acP = ((const float4*)g_Ac) + ((size_t)w * KT) * 32 + lane;

        float2 kb[FT]; float4 ac;
        #pragma unroll
        for (int kt = 0; kt < FT; kt++) kb[kt] = __ldg(kbP + kt * 32);
        ac = __ldg(acP);

        #pragma unroll 1
        for (int jt = 0; jt < KT; jt++) {
            float2 kbn[FT]; float4 acn;
            if (jt + 1 < KT) {
                #pragma unroll
                for (int kt = 0; kt < FT; kt++)
                    kbn[kt] = __ldg(kbP + ((jt + 1) * FT + kt) * 32);
                acn = __ldg(acP + (jt + 1) * 32);
            } else {
                #pragma unroll
                for (int kt = 0; kt < FT; kt++) kbn[kt] = kb[kt];
                acn = ac;
            }

            float d0[4] = {0.f, 0.f, 0.f, 0.f};
            float d1[4] = {0.f, 0.f, 0.f, 0.f};
            #pragma unroll
            for (int kt = 0; kt < FT; kt += 2) {
                mma_tf32(d0, fA[kt],     __float_as_uint(kb[kt].x),     __float_as_uint(kb[kt].y));
                mma_tf32(d1, fA[kt + 1], __float_as_uint(kb[kt + 1].x), __float_as_uint(kb[kt + 1].y));
            }

            int j = 8 * jt + pairOff;
            float2 b1v = *(const float2*)&b1s[j];
            float e0 = ac.x * __expf(d0[0] + d1[0] + b1v.x);
            float e1 = ac.y * __expf(d0[1] + d1[1] + b1v.y);
            float e2 = ac.z * __expf(d0[2] + d1[2] + b1v.x);
            float e3 = ac.w * __expf(d0[3] + d1[3] + b1v.y);
            s0 += e0 + e1; s1 += e2 + e3;

            *(float2*)&eb[rl * 200 + j]       = make_float2(e0, e1);
            *(float2*)&eb[(rl + 8) * 200 + j] = make_float2(e2, e3);

            #pragma unroll
            for (int kt = 0; kt < FT; kt++) kb[kt] = kbn[kt];
            ac = acn;
        }
    }
    // row sums across the 4 lanes of each row group
    s0 += __shfl_xor_sync(~0u, s0, 1); s0 += __shfl_xor_sync(~0u, s0, 2);
    s1 += __shfl_xor_sync(~0u, s1, 1); s1 += __shfl_xor_sync(~0u, s1, 2);
    // padded rows (s==0) get inv=0 so they contribute zeros, never NaN
    const float inv0 = (s0 > 0.f) ? 1.f / s0 : 0.f;
    const float inv1 = (s1 > 0.f) ? 1.f / s1 : 0.f;
    __syncwarp();     // cross-lane visibility of eb before pass B

    if (last_h) {     // single normalized mask write from smem
        #pragma unroll 1
        for (int jt = 0; jt < KT; jt++) {
            int j = 8 * jt + pairOff;
            float2 vA = *(const float2*)&eb[rl * 200 + j];
            float2 vB = *(const float2*)&eb[(rl + 8) * 200 + j];
            if (mA < Nn) {
                float* o = out + ((size_t)b * Nn + mA) * OUTC + Hn * Un + j;
                o[0] = vA.x * inv0; if (j < 198) o[1] = vA.y * inv0;
            }
            if (mB < Nn) {
                float* o = out + ((size_t)b * Nn + mB) * OUTC + Hn * Un + j;
                o[0] = vB.x * inv1; if (j < 198) o[1] = vB.y * inv1;
            }
        }
    }

    // ======== PASS B: NODE = (normalized e) @ X, shuffle-free ========
    // A-frag order: a0=(g,t), a1=(g+8,t), a2=(g,t+4), a3=(g+8,t+4)
    float nC[FT][4];
    #pragma unroll
    for (int t = 0; t < FT; t++) { nC[t][0]=nC[t][1]=nC[t][2]=nC[t][3]=0.f; }

    #pragma unroll 1
    for (int jt = 0; jt < KT; jt++) {
        int jc = 8 * jt + (lane & 3);
        uint32_t u[4];
        u[0] = __float_as_uint(tf32r(eb[rl * 200 + jc]           * inv0));
        u[1] = __float_as_uint(tf32r(eb[(rl + 8) * 200 + jc]     * inv1));
        u[2] = __float_as_uint(tf32r(eb[rl * 200 + jc + 4]       * inv0));
        u[3] = __float_as_uint(tf32r(eb[(rl + 8) * 200 + jc + 4] * inv1));
        #pragma unroll
        for (int ft = 0; ft < FT; ft++) {
            float2 xv = *(const float2*)&XsT[(8 * ft + bRow) * XST + 8 * jt + pairOff];
            mma_tf32(nC[ft], u, __float_as_uint(xv.x), __float_as_uint(xv.y));
        }
    }

    // permute node C -> A fragments (k = f); already normalized
    uint32_t nA[FT][4];
    #pragma unroll
    for (int t = 0; t < FT; t++) {
        float a4[4]; c2a(nC[t], a4, lane);
        #pragma unroll
        for (int q = 0; q < 4; q++) nA[t][q] = __float_as_uint(tf32r(a4[q]));
    }

    // ======== FC: out = node @ fc + b2 ========
    const float2* fbP = ((const float2*)g_Fb) + ((size_t)h * FT * FT) * 32 + lane;
    #pragma unroll 1
    for (int ut = 0; ut < FT; ut++) {
        float oC[4] = {0.f, 0.f, 0.f, 0.f};
        #pragma unroll
        for (int kt = 0; kt < FT; kt++) {
            float2 fb = __ldg(fbP + (ut * FT + kt) * 32);
            mma_tf32(oC, nA[kt], __float_as_uint(fb.x), __float_as_uint(fb.y));
        }
        int u = 8 * ut + pairOff;
        float2 b2v = *(const float2*)&b2s[u];
        if (mA < Nn) {
            float* o = out + ((size_t)b * Nn + mA) * OUTC + h * Un + u;
            o[0] = oC[0] + b2v.x; o[1] = oC[1] + b2v.y;
        }
        if (mB < Nn) {
            float* o = out + ((size_t)b * Nn + mB) * OUTC + h * Un + u;
            o[0] = oC[2] + b2v.x; o[1] = oC[3] + b2v.y;
        }
    }
}

static const size_t SMEM_BYTES =
    (size_t)(Fn * XST + 200 + 64 + MT * EBW) * 4;   // 218,656 B

extern "C" void kernel_launch(void* const* d_in, const int* in_sizes, int n_in,
                              void* d_out, int out_size) {
    const float* X   = (const float*)d_in[0];
    const float* A   = (const float*)d_in[1];
    const float* KER = (const float*)d_in[2];
    const float* P   = (const float*)d_in[3];
    const float* FC  = (const float*)d_in[4];
    const float* B1  = (const float*)d_in[5];
    const float* B2  = (const float*)d_in[6];
    float* out = (float*)d_out;

    const int PREP_TOTAL = GA_N + KB_N + FB_N + AC_N;
    prep_all<<<(PREP_TOTAL + 255) / 256, 256>>>(A, P, KER, FC);

    cudaFuncSetAttribute(gc_kernel, cudaFuncAttributeMaxDynamicSharedMemorySize,
                         (int)SMEM_BYTES);
    gc_kernel<<<Bn * Hn, THREADS, SMEM_BYTES>>>(X, B1, B2, out);
}

// round 14
// speedup vs baseline: 1.8788x; 1.0423x over previous
#include <cuda_runtime.h>
#include <math.h>
#include <stdint.h>

#define Bn   512
#define Nn   199
#define Hn   4
#define Fn   64
#define Un   64
#define OUTC 455           // H*U + N
#define MT   13            // m16 tiles covering 200 rows (208)
#define KT   25            // k/j tiles of 8 covering 200
#define FT   8             // f/u tiles of 8 (64)
#define THREADS 512
#define XST  200           // XsT row stride (== 8 mod 32: conflict-free float2)
#define EBW  (16 * 200)    // e-buffer floats per warp

// Preprocessed operand banks (global, L2-resident)
__device__ float g_Ga[Hn * MT * KT * 32 * 4];  // feat A-frags: G[m][n] tf32
__device__ float g_Kb[Hn * KT * FT * 32 * 2];  // dense B-frags: K[f][j] tf32
__device__ float g_Fb[Hn * FT * FT * 32 * 2];  // fc B-frags: fc[f][u] tf32
__device__ float g_Ac[MT * KT * 32 * 4];       // adjacency in C-frag layout

#define GA_N (Hn * MT * KT * 128)
#define KB_N (Hn * KT * FT * 64)
#define FB_N (Hn * FT * FT * 64)
#define AC_N (MT * KT * 128)

__device__ __forceinline__ float tf32r(float x) {
    asm("cvt.rna.tf32.f32 %0, %0;" : "+f"(x)); return x;
}
__device__ __forceinline__ void mma_tf32(float c[4], const uint32_t a[4],
                                         uint32_t b0, uint32_t b1) {
    asm volatile(
        "mma.sync.aligned.m16n8k8.row.col.f32.tf32.tf32.f32 "
        "{%0,%1,%2,%3}, {%4,%5,%6,%7}, {%8,%9}, {%0,%1,%2,%3};"
        : "+f"(c[0]), "+f"(c[1]), "+f"(c[2]), "+f"(c[3])
        : "r"(a[0]), "r"(a[1]), "r"(a[2]), "r"(a[3]), "r"(b0), "r"(b1));
}
// C-fragment (r,2c even/odd pairs) -> A-fragment (r,k) of the same 8-wide tile
// Output order matches PTX m16n8k8.tf32 A layout:
//   a0=(g, t), a1=(g+8, t), a2=(g, t+4), a3=(g+8, t+4)
__device__ __forceinline__ void c2a(const float c[4], float a[4], int lane) {
    int s0 = (lane & ~3) | ((lane & 3) >> 1);
    int s1 = s0 + 2;
    float v0 = __shfl_sync(~0u, c[0], s0), v1 = __shfl_sync(~0u, c[1], s0);
    float v2 = __shfl_sync(~0u, c[2], s0), v3 = __shfl_sync(~0u, c[3], s0);
    float w0 = __shfl_sync(~0u, c[0], s1), w1 = __shfl_sync(~0u, c[1], s1);
    float w2 = __shfl_sync(~0u, c[2], s1), w3 = __shfl_sync(~0u, c[3], s1);
    bool odd = lane & 1;
    a[0] = odd ? v1 : v0;  a[1] = odd ? v3 : v2;
    a[2] = odd ? w1 : w0;  a[3] = odd ? w3 : w2;
}

// ---------------- fused operand prep (single launch) ----------------
__global__ void prep_all(const float* __restrict__ A, const float* __restrict__ P,
                         const float* __restrict__ KER, const float* __restrict__ FC) {
    int t = blockIdx.x * blockDim.x + threadIdx.x;
    if (t < GA_N) {
        int i = t & 3, lane = (t >> 2) & 31, rest = t >> 7;
        int kt = rest % KT; rest /= KT;
        int mt = rest % MT; int h = rest / MT;
        int row = (lane >> 2) + (i & 1) * 8;
        int kc  = (lane & 3) + ((i >> 1) << 2);
        int m = 16 * mt + row, n = 8 * kt + kc;
        float v = 0.f;
        if (m < Nn && n < Nn) v = tf32r(A[n * Nn + m] * P[(h * Nn + n) * Nn + m]);
        g_Ga[t] = v;
        return;
    }
    t -= GA_N;
    if (t < KB_N) {
        int i = t & 1, lane = (t >> 1) & 31, rest = t >> 6;
        int kt = rest & 7; rest >>= 3;
        int jt = rest % KT; int h = rest / KT;
        int f = 8 * kt + (lane & 3) + 4 * i;
        int j = 8 * jt + (lane >> 2);
        g_Kb[t] = (j < Nn) ? tf32r(KER[(h * Fn + f) * Nn + j]) : 0.f;
        return;
    }
    t -= KB_N;
    if (t < FB_N) {
        int i = t & 1, lane = (t >> 1) & 31, rest = t >> 6;
        int kt = rest & 7; rest >>= 3;
        int ut = rest & 7; int h = rest >> 3;
        int f = 8 * kt + (lane & 3) + 4 * i;
        int u = 8 * ut + (lane >> 2);
        g_Fb[t] = tf32r(FC[(h * Fn + f) * Un + u]);
        return;
    }
    t -= FB_N;
    if (t < AC_N) {
        int i = t & 3, lane = (t >> 2) & 31, rest = t >> 7;
        int jt = rest % KT; int mt = rest / KT;
        int r = (lane >> 2) + (i >> 1) * 8;
        int j = 8 * jt + 2 * (lane & 3) + (i & 1);
        int m = 16 * mt + r;
        g_Ac[t] = (m < Nn && j < Nn) ? A[m * Nn + j] : 0.f;
    }
}

// ---------------- main fused kernel ----------------
__global__ __launch_bounds__(THREADS, 1)
void gc_kernel(const float* __restrict__ X, const float* __restrict__ B1,
               const float* __restrict__ B2, float* __restrict__ out)
{
    extern __shared__ float smem[];
    float* XsT  = smem;                 // [64][XST] tf32 X^T, pair-permuted cols
    float* b1s  = XsT + Fn * XST;       // [200]
    float* b2s  = b1s + 200;            // [64]
    float* ebuf = b2s + 64;             // [MT][16][200] per-warp e staging

    const int b = blockIdx.x / Hn;
    const int h = blockIdx.x - b * Hn;
    const int tid = threadIdx.x;
    const int w = tid >> 5;
    const int lane = tid & 31;
    const bool last_h = (h == Hn - 1);

    for (int i = tid; i < 200 * Fn; i += THREADS) {
        int n = i >> 6, f = i & 63;
        float v = (n < Nn) ? X[((size_t)b * Nn + n) * Fn + f] : 0.f;
        // pair permutation: slot pair 2c holds (n=c, n=c+4) of each 8-tile
        int col = (n & ~7) | ((n & 3) << 1) | ((n >> 2) & 1);
        XsT[f * XST + col] = tf32r(v);
    }
    for (int i = tid; i < 200; i += THREADS) b1s[i] = (i < Nn) ? B1[h * Nn + i] : 0.f;
    if (tid < Un) b2s[tid] = B2[h * Un + tid];
    __syncthreads();

    if (w >= MT) return;
    const int m0 = 16 * w;
    const int rl = lane >> 2;               // local row within m16 tile
    const int mA = m0 + rl;                 // row for c0/c1
    const int mB = mA + 8;                  // row for c2/c3
    const int pairOff = 2 * (lane & 3);     // pair slot within tile
    const int bRow = rl;                    // n-dim row within B tile
    float* eb = ebuf + w * EBW;             // [16][200]

    // ======== FEAT: fC[ft] = G(m-tile) @ X  (k = 200 nodes) ========
    float fC[FT][4];
    #pragma unroll
    for (int t = 0; t < FT; t++) { fC[t][0]=fC[t][1]=fC[t][2]=fC[t][3]=0.f; }
    {
        const float4* gaP = ((const float4*)g_Ga) + ((size_t)(h * MT + w) * KT) * 32 + lane;
        float4 ga = __ldg(gaP);
        #pragma unroll 1
        for (int kt = 0; kt < KT; kt++) {
            float4 gan = (kt + 1 < KT) ? __ldg(gaP + (kt + 1) * 32) : ga;
            uint32_t a[4] = { __float_as_uint(ga.x), __float_as_uint(ga.y),
                              __float_as_uint(ga.z), __float_as_uint(ga.w) };
            #pragma unroll
            for (int ft = 0; ft < FT; ft++) {
                float2 xv = *(const float2*)&XsT[(8 * ft + bRow) * XST + 8 * kt + pairOff];
                mma_tf32(fC[ft], a, __float_as_uint(xv.x), __float_as_uint(xv.y));
            }
            ga = gan;
        }
    }
    // permute feat C -> A fragments (k = f)
    uint32_t fA[FT][4];
    #pragma unroll
    for (int t = 0; t < FT; t++) {
        float a4[4]; c2a(fC[t], a4, lane);
        #pragma unroll
        for (int q = 0; q < 4; q++) fA[t][q] = __float_as_uint(tf32r(a4[q]));
    }

    // ======== PASS A: DENSE + masked exp -> smem e-buffer ========
    // Ping-pong unroll-by-2: tiles A (even jt) and B (odd jt) use separate
    // register sets; no copies; two independent dense chains in flight.
    float s0 = 0.f, s1 = 0.f;
    {
        const float2* kbP = ((const float2*)g_Kb) + ((size_t)h * KT * FT) * 32 + lane;
        const float4* acP = ((const float4*)g_Ac) + ((size_t)w * KT) * 32 + lane;

        float2 kbA[FT], kbB[FT];
        float4 acA, acB;
        #pragma unroll
        for (int kt = 0; kt < FT; kt++) kbA[kt] = __ldg(kbP + kt * 32);
        acA = __ldg(acP);

        #pragma unroll 1
        for (int it = 0; it < 13; it++) {
            const int jtA = 2 * it;
            const int jtB = jtA + 1;
            const bool hasB = (jtB < KT);

            if (hasB) {      // prefetch tile B operands
                #pragma unroll
                for (int kt = 0; kt < FT; kt++)
                    kbB[kt] = __ldg(kbP + (jtB * FT + kt) * 32);
                acB = __ldg(acP + jtB * 32);
            }

            // ---- tile A: 4 accumulators, chain depth 2
            {
                float d0[4]={0,0,0,0}, d1[4]={0,0,0,0}, d2[4]={0,0,0,0}, d3[4]={0,0,0,0};
                mma_tf32(d0, fA[0], __float_as_uint(kbA[0].x), __float_as_uint(kbA[0].y));
                mma_tf32(d1, fA[1], __float_as_uint(kbA[1].x), __float_as_uint(kbA[1].y));
                mma_tf32(d2, fA[2], __float_as_uint(kbA[2].x), __float_as_uint(kbA[2].y));
                mma_tf32(d3, fA[3], __float_as_uint(kbA[3].x), __float_as_uint(kbA[3].y));
                mma_tf32(d0, fA[4], __float_as_uint(kbA[4].x), __float_as_uint(kbA[4].y));
                mma_tf32(d1, fA[5], __float_as_uint(kbA[5].x), __float_as_uint(kbA[5].y));
                mma_tf32(d2, fA[6], __float_as_uint(kbA[6].x), __float_as_uint(kbA[6].y));
                mma_tf32(d3, fA[7], __float_as_uint(kbA[7].x), __float_as_uint(kbA[7].y));

                int j = 8 * jtA + pairOff;
                float2 b1v = *(const float2*)&b1s[j];
                float e0 = acA.x * __expf(d0[0] + d1[0] + d2[0] + d3[0] + b1v.x);
                float e1 = acA.y * __expf(d0[1] + d1[1] + d2[1] + d3[1] + b1v.y);
                float e2 = acA.z * __expf(d0[2] + d1[2] + d2[2] + d3[2] + b1v.x);
                float e3 = acA.w * __expf(d0[3] + d1[3] + d2[3] + d3[3] + b1v.y);
                s0 += e0 + e1; s1 += e2 + e3;
                *(float2*)&eb[rl * 200 + j]       = make_float2(e0, e1);
                *(float2*)&eb[(rl + 8) * 200 + j] = make_float2(e2, e3);
            }

            if (jtA + 2 < KT) {  // prefetch next tile A operands
                #pragma unroll
                for (int kt = 0; kt < FT; kt++)
                    kbA[kt] = __ldg(kbP + ((jtA + 2) * FT + kt) * 32);
                acA = __ldg(acP + (jtA + 2) * 32);
            }

            // ---- tile B
            if (hasB) {
                float d0[4]={0,0,0,0}, d1[4]={0,0,0,0}, d2[4]={0,0,0,0}, d3[4]={0,0,0,0};
                mma_tf32(d0, fA[0], __float_as_uint(kbB[0].x), __float_as_uint(kbB[0].y));
                mma_tf32(d1, fA[1], __float_as_uint(kbB[1].x), __float_as_uint(kbB[1].y));
                mma_tf32(d2, fA[2], __float_as_uint(kbB[2].x), __float_as_uint(kbB[2].y));
                mma_tf32(d3, fA[3], __float_as_uint(kbB[3].x), __float_as_uint(kbB[3].y));
                mma_tf32(d0, fA[4], __float_as_uint(kbB[4].x), __float_as_uint(kbB[4].y));
                mma_tf32(d1, fA[5], __float_as_uint(kbB[5].x), __float_as_uint(kbB[5].y));
                mma_tf32(d2, fA[6], __float_as_uint(kbB[6].x), __float_as_uint(kbB[6].y));
                mma_tf32(d3, fA[7], __float_as_uint(kbB[7].x), __float_as_uint(kbB[7].y));

                int j = 8 * jtB + pairOff;
                float2 b1v = *(const float2*)&b1s[j];
                float e0 = acB.x * __expf(d0[0] + d1[0] + d2[0] + d3[0] + b1v.x);
                float e1 = acB.y * __expf(d0[1] + d1[1] + d2[1] + d3[1] + b1v.y);
                float e2 = acB.z * __expf(d0[2] + d1[2] + d2[2] + d3[2] + b1v.x);
                float e3 = acB.w * __expf(d0[3] + d1[3] + d2[3] + d3[3] + b1v.y);
                s0 += e0 + e1; s1 += e2 + e3;
                *(float2*)&eb[rl * 200 + j]       = make_float2(e0, e1);
                *(float2*)&eb[(rl + 8) * 200 + j] = make_float2(e2, e3);
            }
        }
    }
    // row sums across the 4 lanes of each row group
    s0 += __shfl_xor_sync(~0u, s0, 1); s0 += __shfl_xor_sync(~0u, s0, 2);
    s1 += __shfl_xor_sync(~0u, s1, 1); s1 += __shfl_xor_sync(~0u, s1, 2);
    // padded rows (s==0) get inv=0 so they contribute zeros, never NaN
    const float inv0 = (s0 > 0.f) ? 1.f / s0 : 0.f;
    const float inv1 = (s1 > 0.f) ? 1.f / s1 : 0.f;
    __syncwarp();     // cross-lane visibility of eb before pass B

    if (last_h) {     // single normalized mask write from smem
        #pragma unroll 1
        for (int jt = 0; jt < KT; jt++) {
            int j = 8 * jt + pairOff;
            float2 vA = *(const float2*)&eb[rl * 200 + j];
            float2 vB = *(const float2*)&eb[(rl + 8) * 200 + j];
            if (mA < Nn) {
                float* o = out + ((size_t)b * Nn + mA) * OUTC + Hn * Un + j;
                o[0] = vA.x * inv0; if (j < 198) o[1] = vA.y * inv0;
            }
            if (mB < Nn) {
                float* o = out + ((size_t)b * Nn + mB) * OUTC + Hn * Un + j;
                o[0] = vB.x * inv1; if (j < 198) o[1] = vB.y * inv1;
            }
        }
    }

    // ======== PASS B: NODE = (normalized e) @ X, shuffle-free ========
    // A-frag order: a0=(g,t), a1=(g+8,t), a2=(g,t+4), a3=(g+8,t+4)
    float nC[FT][4];
    #pragma unroll
    for (int t = 0; t < FT; t++) { nC[t][0]=nC[t][1]=nC[t][2]=nC[t][3]=0.f; }

    #pragma unroll 1
    for (int jt = 0; jt < KT; jt++) {
        int jc = 8 * jt + (lane & 3);
        uint32_t u[4];
        u[0] = __float_as_uint(tf32r(eb[rl * 200 + jc]           * inv0));
        u[1] = __float_as_uint(tf32r(eb[(rl + 8) * 200 + jc]     * inv1));
        u[2] = __float_as_uint(tf32r(eb[rl * 200 + jc + 4]       * inv0));
        u[3] = __float_as_uint(tf32r(eb[(rl + 8) * 200 + jc + 4] * inv1));
        #pragma unroll
        for (int ft = 0; ft < FT; ft++) {
            float2 xv = *(const float2*)&XsT[(8 * ft + bRow) * XST + 8 * jt + pairOff];
            mma_tf32(nC[ft], u, __float_as_uint(xv.x), __float_as_uint(xv.y));
        }
    }

    // permute node C -> A fragments (k = f); already normalized
    uint32_t nA[FT][4];
    #pragma unroll
    for (int t = 0; t < FT; t++) {
        float a4[4]; c2a(nC[t], a4, lane);
        #pragma unroll
        for (int q = 0; q < 4; q++) nA[t][q] = __float_as_uint(tf32r(a4[q]));
    }

    // ======== FC: out = node @ fc + b2 ========
    const float2* fbP = ((const float2*)g_Fb) + ((size_t)h * FT * FT) * 32 + lane;
    #pragma unroll 1
    for (int ut = 0; ut < FT; ut++) {
        float oC0[4] = {0.f, 0.f, 0.f, 0.f};
        float oC1[4] = {0.f, 0.f, 0.f, 0.f};
        #pragma unroll
        for (int kt = 0; kt < FT; kt += 2) {
            float2 fb0 = __ldg(fbP + (ut * FT + kt) * 32);
            float2 fb1 = __ldg(fbP + (ut * FT + kt + 1) * 32);
            mma_tf32(oC0, nA[kt],     __float_as_uint(fb0.x), __float_as_uint(fb0.y));
            mma_tf32(oC1, nA[kt + 1], __float_as_uint(fb1.x), __float_as_uint(fb1.y));
        }
        int u = 8 * ut + pairOff;
        float2 b2v = *(const float2*)&b2s[u];
        if (mA < Nn) {
            float* o = out + ((size_t)b * Nn + mA) * OUTC + h * Un + u;
            o[0] = oC0[0] + oC1[0] + b2v.x; o[1] = oC0[1] + oC1[1] + b2v.y;
        }
        if (mB < Nn) {
            float* o = out + ((size_t)b * Nn + mB) * OUTC + h * Un + u;
            o[0] = oC0[2] + oC1[2] + b2v.x; o[1] = oC0[3] + oC1[3] + b2v.y;
        }
    }
}

static const size_t SMEM_BYTES =
    (size_t)(Fn * XST + 200 + 64 + MT * EBW) * 4;   // 218,656 B

extern "C" void kernel_launch(void* const* d_in, const int* in_sizes, int n_in,
                              void* d_out, int out_size) {
    const float* X   = (const float*)d_in[0];
    const float* A   = (const float*)d_in[1];
    const float* KER = (const float*)d_in[2];
    const float* P   = (const float*)d_in[3];
    const float* FC  = (const float*)d_in[4];
    const float* B1  = (const float*)d_in[5];
    const float* B2  = (const float*)d_in[6];
    float* out = (float*)d_out;

    const int PREP_TOTAL = GA_N + KB_N + FB_N + AC_N;
    prep_all<<<(PREP_TOTAL + 255) / 256, 256>>>(A, P, KER, FC);

    cudaFuncSetAttribute(gc_kernel, cudaFuncAttributeMaxDynamicSharedMemorySize,
                         (int)SMEM_BYTES);
    gc_kernel<<<Bn * Hn, THREADS, SMEM_BYTES>>>(X, B1, B2, out);
}

// round 16
// speedup vs baseline: 2.1214x; 1.1291x over previous
#include <cuda_runtime.h>
#include <cuda_fp16.h>
#include <math.h>
#include <stdint.h>

#define Bn   512
#define Nn   199
#define Hn   4
#define Fn   64
#define Un   64
#define OUTC 455           // H*U + N
#define MT   13            // m16 tiles covering 200 rows (208)
#define JT8  25            // j-tiles of 8 (dense output)
#define NT16 13            // node k16-tiles (208)
#define FKT  4             // f k16-tiles (64)
#define FT   8             // f/u 8-tiles
#define THREADS 512
#define XSTh 208           // XsT half-stride (416B == 32 mod 128: conflict-free)
#define EBWh (16 * 208)    // e-buffer halves per warp

// Preprocessed fp16 operand banks (global, L2-resident)
__device__ uint32_t g_GaH[Hn * MT * NT16 * 128];  // feat A-frags (k16)
__device__ uint32_t g_KbH[Hn * JT8 * FKT * 64];   // dense B-frags (k16)
__device__ uint32_t g_FbH[Hn * FT * FKT * 64];    // fc B-frags (k16)
__device__ float    g_Ac [MT * JT8 * 128];        // adjacency C-frag fp32

#define GA16_N (Hn * MT * NT16 * 128)
#define KB16_N (Hn * JT8 * FKT * 64)
#define FB16_N (Hn * FT * FKT * 64)
#define AC_N   (MT * JT8 * 128)

__device__ __forceinline__ void mma_f16(float c[4],
    uint32_t a0, uint32_t a1, uint32_t a2, uint32_t a3,
    uint32_t b0, uint32_t b1) {
    asm volatile(
        "mma.sync.aligned.m16n8k16.row.col.f32.f16.f16.f32 "
        "{%0,%1,%2,%3}, {%4,%5,%6,%7}, {%8,%9}, {%0,%1,%2,%3};"
        : "+f"(c[0]), "+f"(c[1]), "+f"(c[2]), "+f"(c[3])
        : "r"(a0), "r"(a1), "r"(a2), "r"(a3), "r"(b0), "r"(b1));
}
__device__ __forceinline__ uint32_t pkh2(float lo, float hi) {
    __half2 h = __floats2half2_rn(lo, hi);       // .x = lo (low 16 bits)
    return *reinterpret_cast<uint32_t*>(&h);
}
__device__ __forceinline__ uint32_t hmul2u(uint32_t a, __half2 s) {
    __half2 av = *reinterpret_cast<__half2*>(&a);
    __half2 r = __hmul2(av, s);
    return *reinterpret_cast<uint32_t*>(&r);
}
// node column w (0..15) -> permuted slot: pairs (2c,2c+1,2c+8,2c+9) adjacent
__device__ __forceinline__ int nslot(int w) {
    return 4 * ((w & 7) >> 1) + (w & 1) + 2 * (w >> 3);
}

// ---------------- fused operand prep (single launch) ----------------
__global__ void prep_all(const float* __restrict__ A, const float* __restrict__ P,
                         const float* __restrict__ KER, const float* __restrict__ FC) {
    int t = blockIdx.x * blockDim.x + threadIdx.x;
    if (t < GA16_N) {
        int r = t & 3, lane = (t >> 2) & 31, rest = t >> 7;
        int kt = rest % NT16; rest /= NT16;
        int mt = rest % MT;  int h = rest / MT;
        int m  = 16 * mt + (lane >> 2) + (r & 1) * 8;
        int n0 = 16 * kt + 2 * (lane & 3) + (r >> 1) * 8;
        float v0 = (m < Nn && n0     < Nn) ? A[n0 * Nn + m] * P[(h * Nn + n0) * Nn + m] : 0.f;
        float v1 = (m < Nn && n0 + 1 < Nn) ? A[(n0 + 1) * Nn + m] * P[(h * Nn + n0 + 1) * Nn + m] : 0.f;
        g_GaH[t] = pkh2(v0, v1);
        return;
    }
    t -= GA16_N;
    if (t < KB16_N) {
        int r = t & 1, lane = (t >> 1) & 31, rest = t >> 6;
        int kt = rest & 3; rest >>= 2;
        int jt = rest % JT8; int h = rest / JT8;
        int f0 = 16 * kt + 2 * (lane & 3) + r * 8;
        int j  = 8 * jt + (lane >> 2);
        float v0 = (j < Nn) ? KER[(h * Fn + f0) * Nn + j] : 0.f;
        float v1 = (j < Nn) ? KER[(h * Fn + f0 + 1) * Nn + j] : 0.f;
        g_KbH[t] = pkh2(v0, v1);
        return;
    }
    t -= KB16_N;
    if (t < FB16_N) {
        int r = t & 1, lane = (t >> 1) & 31, rest = t >> 6;
        int kt = rest & 3; rest >>= 2;
        int ut = rest & 7; int h = rest >> 3;
        int f0 = 16 * kt + 2 * (lane & 3) + r * 8;
        int u  = 8 * ut + (lane >> 2);
        g_FbH[t] = pkh2(FC[(h * Fn + f0) * Un + u], FC[(h * Fn + f0 + 1) * Un + u]);
        return;
    }
    t -= FB16_N;
    if (t < AC_N) {
        int i = t & 3, lane = (t >> 2) & 31, rest = t >> 7;
        int jt = rest % JT8; int mt = rest / JT8;
        int r = (lane >> 2) + (i >> 1) * 8;
        int j = 8 * jt + 2 * (lane & 3) + (i & 1);
        int m = 16 * mt + r;
        g_Ac[t] = (m < Nn && j < Nn) ? A[m * Nn + j] : 0.f;
    }
}

// ---------------- main fused kernel ----------------
__global__ __launch_bounds__(THREADS, 2)
void gc_kernel(const float* __restrict__ X, const float* __restrict__ B1,
               const float* __restrict__ B2, float* __restrict__ out)
{
    extern __shared__ __align__(16) char smraw[];
    __half* XsT  = (__half*)smraw;             // [64][XSTh] fp16 X^T, pair-permuted
    __half* ebuf = XsT + Fn * XSTh;            // [MT][16][XSTh] fp16 e staging
    float*  b1s  = (float*)(ebuf + MT * EBWh); // [200] fp32

    const int b = blockIdx.x / Hn;
    const int h = blockIdx.x - b * Hn;
    const int tid = threadIdx.x;
    const int w = tid >> 5;
    const int lane = tid & 31;
    const bool last_h = (h == Hn - 1);

    for (int i = tid; i < 208 * Fn; i += THREADS) {
        int n = i >> 6, f = i & 63;
        float v = (n < Nn) ? X[((size_t)b * Nn + n) * Fn + f] : 0.f;
        int col = (n & ~15) + nslot(n & 15);
        XsT[f * XSTh + col] = __float2half_rn(v);
    }
    // zero the pad region of every warp's e-buffer (node cols 192..207)
    for (int i = tid; i < MT * 16 * 8; i += THREADS) {
        int wb = i >> 7, row = (i >> 3) & 15, cc = i & 7;
        *(uint32_t*)&ebuf[wb * EBWh + row * XSTh + 192 + 2 * cc] = 0u;
    }
    for (int i = tid; i < 200; i += THREADS) b1s[i] = (i < Nn) ? B1[h * Nn + i] : 0.f;
    __syncthreads();

    if (w >= MT) return;
    const int m0 = 16 * w;
    const int g = lane >> 2;                 // row group within tile
    const int q = lane & 3;
    const int mA = m0 + g;                   // rows for c0/c1
    const int mB = mA + 8;                   // rows for c2/c3
    const int pairOff = 2 * q;
    __half* eb = ebuf + w * EBWh;            // [16][XSTh]

    // ======== FEAT: fC[ft] = G(m-tile) @ X  (k = 208 nodes, 13 k16-tiles) ====
    float fC[FT][4];
    #pragma unroll
    for (int t = 0; t < FT; t++) { fC[t][0]=fC[t][1]=fC[t][2]=fC[t][3]=0.f; }
    {
        const uint4* gaP = ((const uint4*)g_GaH) + ((size_t)(h * MT + w) * NT16) * 32 + lane;
        uint4 ga = __ldg(gaP);
        #pragma unroll 1
        for (int kt = 0; kt < NT16; kt++) {
            uint4 gan = (kt + 1 < NT16) ? __ldg(gaP + (kt + 1) * 32) : ga;
            #pragma unroll
            for (int ft = 0; ft < FT; ft++) {
                uint2 xv = *(const uint2*)&XsT[(8 * ft + g) * XSTh + 16 * kt + 4 * q];
                mma_f16(fC[ft], ga.x, ga.y, ga.z, ga.w, xv.x, xv.y);
            }
            ga = gan;
        }
    }
    // pack feat C -> k16 A-frags in-lane (adjacent C cols = fp16x2 pair; NO shuffles)
    uint32_t fA[FKT][4];
    #pragma unroll
    for (int kt = 0; kt < FKT; kt++) {
        fA[kt][0] = pkh2(fC[2*kt][0],   fC[2*kt][1]);
        fA[kt][1] = pkh2(fC[2*kt][2],   fC[2*kt][3]);
        fA[kt][2] = pkh2(fC[2*kt+1][0], fC[2*kt+1][1]);
        fA[kt][3] = pkh2(fC[2*kt+1][2], fC[2*kt+1][3]);
    }

    // ======== PASS A: DENSE + masked exp -> fp16 e-buffer (+ raw fp32 mask) ===
    float s0 = 0.f, s1 = 0.f;
    {
        const uint2*  kbP = ((const uint2*)g_KbH) + (size_t)h * (JT8 * FKT * 32) + lane;
        const float4* acP = ((const float4*)g_Ac) + (size_t)w * (JT8 * 32) + lane;

        uint2 kb[FKT]; float4 ac;
        #pragma unroll
        for (int kt = 0; kt < FKT; kt++) kb[kt] = __ldg(kbP + kt * 32);
        ac = __ldg(acP);

        #pragma unroll 1
        for (int jt = 0; jt < JT8; jt++) {
            uint2 kbn[FKT]; float4 acn;
            if (jt + 1 < JT8) {
                #pragma unroll
                for (int kt = 0; kt < FKT; kt++)
                    kbn[kt] = __ldg(kbP + ((jt + 1) * FKT + kt) * 32);
                acn = __ldg(acP + (jt + 1) * 32);
            } else {
                #pragma unroll
                for (int kt = 0; kt < FKT; kt++) kbn[kt] = kb[kt];
                acn = ac;
            }

            float d0[4] = {0.f,0.f,0.f,0.f};
            float d1[4] = {0.f,0.f,0.f,0.f};
            mma_f16(d0, fA[0][0],fA[0][1],fA[0][2],fA[0][3], kb[0].x, kb[0].y);
            mma_f16(d1, fA[1][0],fA[1][1],fA[1][2],fA[1][3], kb[1].x, kb[1].y);
            mma_f16(d0, fA[2][0],fA[2][1],fA[2][2],fA[2][3], kb[2].x, kb[2].y);
            mma_f16(d1, fA[3][0],fA[3][1],fA[3][2],fA[3][3], kb[3].x, kb[3].y);

            int j = 8 * jt + pairOff;
            float2 b1v = *(const float2*)&b1s[j];
            float e0 = ac.x * __expf(d0[0] + d1[0] + b1v.x);
            float e1 = ac.y * __expf(d0[1] + d1[1] + b1v.y);
            float e2 = ac.z * __expf(d0[2] + d1[2] + b1v.x);
            float e3 = ac.w * __expf(d0[3] + d1[3] + b1v.y);
            s0 += e0 + e1; s1 += e2 + e3;

            int ecol = 16 * (jt >> 1) + 4 * q + 2 * (jt & 1);   // permuted slot pair
            *(uint32_t*)&eb[g * XSTh + ecol]       = pkh2(e0, e1);
            *(uint32_t*)&eb[(g + 8) * XSTh + ecol] = pkh2(e2, e3);

            if (last_h) {   // raw fp32 mask; same thread rescales after sums
                if (mA < Nn) {
                    float* o = out + ((size_t)b * Nn + mA) * OUTC + Hn * Un + j;
                    o[0] = e0; if (j < 198) o[1] = e1;
                }
                if (mB < Nn) {
                    float* o = out + ((size_t)b * Nn + mB) * OUTC + Hn * Un + j;
                    o[0] = e2; if (j < 198) o[1] = e3;
                }
            }
            #pragma unroll
            for (int kt = 0; kt < FKT; kt++) kb[kt] = kbn[kt];
            ac = acn;
        }
    }
    s0 += __shfl_xor_sync(~0u, s0, 1); s0 += __shfl_xor_sync(~0u, s0, 2);
    s1 += __shfl_xor_sync(~0u, s1, 1); s1 += __shfl_xor_sync(~0u, s1, 2);
    const float inv0 = (s0 > 0.f) ? 1.f / s0 : 0.f;
    const float inv1 = (s1 > 0.f) ? 1.f / s1 : 0.f;
    __syncwarp();     // cross-lane visibility of eb before pass B

    if (last_h) {     // rescale raw mask in-place (same thread wrote it)
        #pragma unroll 1
        for (int jt = 0; jt < JT8; jt++) {
            int j = 8 * jt + pairOff;
            if (mA < Nn) {
                float* o = out + ((size_t)b * Nn + mA) * OUTC + Hn * Un + j;
                o[0] *= inv0; if (j < 198) o[1] *= inv0;
            }
            if (mB < Nn) {
                float* o = out + ((size_t)b * Nn + mB) * OUTC + Hn * Un + j;
                o[0] *= inv1; if (j < 198) o[1] *= inv1;
            }
        }
    }

    // ======== PASS B: NODE = (e*inv) @ X over 13 j k16-tiles, shuffle-free ====
    const __half2 hi0 = __float2half2_rn(inv0);
    const __half2 hi1 = __float2half2_rn(inv1);
    float nC[FT][4];
    #pragma unroll
    for (int t = 0; t < FT; t++) { nC[t][0]=nC[t][1]=nC[t][2]=nC[t][3]=0.f; }

    #pragma unroll 1
    for (int jt = 0; jt < NT16; jt++) {
        uint2 aLo = *(const uint2*)&eb[g * XSTh + 16 * jt + 4 * q];       // (g, k), (g, k+8)
        uint2 aHi = *(const uint2*)&eb[(g + 8) * XSTh + 16 * jt + 4 * q]; // (g+8, ...)
        uint32_t a0 = hmul2u(aLo.x, hi0), a2 = hmul2u(aLo.y, hi0);
        uint32_t a1 = hmul2u(aHi.x, hi1), a3 = hmul2u(aHi.y, hi1);
        #pragma unroll
        for (int ft = 0; ft < FT; ft++) {
            uint2 xv = *(const uint2*)&XsT[(8 * ft + g) * XSTh + 16 * jt + 4 * q];
            mma_f16(nC[ft], a0, a1, a2, a3, xv.x, xv.y);
        }
    }

    // pack node C -> k16 A-frags in-lane (normalized already; NO shuffles)
    uint32_t nA[FKT][4];
    #pragma unroll
    for (int kt = 0; kt < FKT; kt++) {
        nA[kt][0] = pkh2(nC[2*kt][0],   nC[2*kt][1]);
        nA[kt][1] = pkh2(nC[2*kt][2],   nC[2*kt][3]);
        nA[kt][2] = pkh2(nC[2*kt+1][0], nC[2*kt+1][1]);
        nA[kt][3] = pkh2(nC[2*kt+1][2], nC[2*kt+1][3]);
    }

    // ======== FC: out = node @ fc + b2 ========
    const uint2* fbP = ((const uint2*)g_FbH) + (size_t)h * (FT * FKT * 32) + lane;
    #pragma unroll 1
    for (int ut = 0; ut < FT; ut++) {
        float o0[4] = {0.f,0.f,0.f,0.f};
        float o1[4] = {0.f,0.f,0.f,0.f};
        uint2 fb0 = __ldg(fbP + (ut * FKT + 0) * 32);
        uint2 fb1 = __ldg(fbP + (ut * FKT + 1) * 32);
        uint2 fb2 = __ldg(fbP + (ut * FKT + 2) * 32);
        uint2 fb3 = __ldg(fbP + (ut * FKT + 3) * 32);
        mma_f16(o0, nA[0][0],nA[0][1],nA[0][2],nA[0][3], fb0.x, fb0.y);
        mma_f16(o1, nA[1][0],nA[1][1],nA[1][2],nA[1][3], fb1.x, fb1.y);
        mma_f16(o0, nA[2][0],nA[2][1],nA[2][2],nA[2][3], fb2.x, fb2.y);
        mma_f16(o1, nA[3][0],nA[3][1],nA[3][2],nA[3][3], fb3.x, fb3.y);

        int u = 8 * ut + pairOff;
        float b2x = __ldg(&B2[h * Un + u]);
        float b2y = __ldg(&B2[h * Un + u + 1]);
        if (mA < Nn) {
            float* o = out + ((size_t)b * Nn + mA) * OUTC + h * Un + u;
            o[0] = o0[0] + o1[0] + b2x; o[1] = o0[1] + o1[1] + b2y;
        }
        if (mB < Nn) {
            float* o = out + ((size_t)b * Nn + mB) * OUTC + h * Un + u;
            o[0] = o0[2] + o1[2] + b2x; o[1] = o0[3] + o1[3] + b2y;
        }
    }
}

static const size_t SMEM_BYTES =
    (size_t)(Fn * XSTh + MT * EBWh) * 2 + 200 * 4;   // 113,952 B (2 blocks/SM)

extern "C" void kernel_launch(void* const* d_in, const int* in_sizes, int n_in,
                              void* d_out, int out_size) {
    const float* X   = (const float*)d_in[0];
    const float* A   = (const float*)d_in[1];
    const float* KER = (const float*)d_in[2];
    const float* P   = (const float*)d_in[3];
    const float* FC  = (const float*)d_in[4];
    const float* B1  = (const float*)d_in[5];
    const float* B2  = (const float*)d_in[6];
    float* out = (float*)d_out;

    const int PREP_TOTAL = GA16_N + KB16_N + FB16_N + AC_N;
    prep_all<<<(PREP_TOTAL + 255) / 256, 256>>>(A, P, KER, FC);

    cudaFuncSetAttribute(gc_kernel, cudaFuncAttributeMaxDynamicSharedMemorySize,
                         (int)SMEM_BYTES);
    gc_kernel<<<Bn * Hn, THREADS, SMEM_BYTES>>>(X, B1, B2, out);
}